// round 2
// baseline (speedup 1.0000x reference)
#include <cuda_runtime.h>
#include <math.h>

#define BNB  2
#define NPTS 2048
#define CCH  256
#define NH   4
#define HDIM 64
#define NL   4
#define BHN  (BNB*NH)
#define EPSBN 1e-5f
#define KSPL 4
#define KCH  (NPTS/KSPL)

// ---------------- scratch (device globals; no allocation allowed) -------------
__device__ float g_bufA[BNB*CCH*NPTS];
__device__ float g_bufB[BNB*CCH*NPTS];
__device__ float g_q  [BHN*HDIM*NPTS];
__device__ float g_k  [BHN*HDIM*NPTS];
__device__ float g_v  [BHN*HDIM*NPTS];
__device__ float g_xr [BHN*HDIM*NPTS];
__device__ float g_S  [(size_t)BHN*NPTS*NPTS];   // raw scores, 134 MB
__device__ float g_mx [BHN*NPTS];
__device__ float g_rs [BHN*NPTS];
__device__ float g_cs [BHN*NPTS];

// fast exp on the FMA pipe: exp(x) = 2^(x*log2e), |rel err| ~1e-7
__device__ __forceinline__ float fexp(float x) {
    x = fmaxf(x, -80.f);
    float t = fmaf(x, 1.44269504f, 12582912.f);   // round(x*log2e) in low bits
    int   e = __float_as_int(t) << 23;
    float r = t - 12582912.f;
    float f = fmaf(x, 1.44269504f, -r);            // frac in [-0.5, 0.5]
    float p = 1.54035304e-4f;
    p = fmaf(p, f, 1.33335581e-3f);
    p = fmaf(p, f, 9.61812911e-3f);
    p = fmaf(p, f, 5.55041087e-2f);
    p = fmaf(p, f, 2.40226507e-1f);
    p = fmaf(p, f, 6.93147181e-1f);
    p = fmaf(p, f, 1.0f);
    return __int_as_float(__float_as_int(p) + e);
}

// ---------------- transposes ----------------
__global__ void k_transpose_in(const float* __restrict__ x, float* __restrict__ h) {
    __shared__ float tile[32][33];
    int b = blockIdx.z;
    int n0 = blockIdx.x * 32, c0 = blockIdx.y * 32;
    int tx = threadIdx.x, ty = threadIdx.y;
    for (int i = ty; i < 32; i += 8)
        tile[i][tx] = x[(size_t)b*NPTS*CCH + (size_t)(n0+i)*CCH + c0 + tx];
    __syncthreads();
    for (int i = ty; i < 32; i += 8)
        h[(size_t)b*CCH*NPTS + (size_t)(c0+i)*NPTS + n0 + tx] = tile[tx][i];
}

__global__ void k_transpose_out(const float* __restrict__ h, float* __restrict__ out) {
    __shared__ float tile[32][33];
    int b = blockIdx.z;
    int c0 = blockIdx.x * 32, n0 = blockIdx.y * 32;
    int tx = threadIdx.x, ty = threadIdx.y;
    for (int i = ty; i < 32; i += 8)
        tile[i][tx] = h[(size_t)b*CCH*NPTS + (size_t)(c0+i)*NPTS + n0 + tx];
    __syncthreads();
    for (int i = ty; i < 32; i += 8)
        out[(size_t)b*NPTS*CCH + (size_t)(n0+i)*CCH + c0 + tx] = tile[tx][i];
}

// ---------------- full-channel GEMM (MLP / proj), tile 64o x 128n, K step 16 ----
__global__ __launch_bounds__(256)
void k_mlp(const float* __restrict__ W, const float* __restrict__ in,
           float* __restrict__ out, const float* __restrict__ bvec,
           const float* __restrict__ gvec, const float* __restrict__ bevec,
           int relu) {
    __shared__ float As[64][16];    // [oo][kk]
    __shared__ float Bs[16][128];   // [kk][nn]
    int b  = blockIdx.z;
    int n0 = blockIdx.x * 128, o0 = blockIdx.y * 64;
    int t  = threadIdx.x, tx = t & 15, ty = t >> 4;
    const float* inb = in + (size_t)b*CCH*NPTS;
    int aoo = t >> 2, akk = (t & 3) * 4;
    float acc[4][8] = {};
    for (int kc = 0; kc < CCH; kc += 16) {
        *(float4*)&As[aoo][akk] = *(const float4*)&W[(size_t)(o0+aoo)*CCH + kc + akk];
        #pragma unroll
        for (int hf = 0; hf < 2; hf++) {
            int idx = hf*1024 + t*4;
            int kk = idx >> 7, nn = idx & 127;
            *(float4*)&Bs[kk][nn] = *(const float4*)&inb[(size_t)(kc+kk)*NPTS + n0 + nn];
        }
        __syncthreads();
        #pragma unroll
        for (int kk = 0; kk < 16; kk++) {
            float a[4];
            #pragma unroll
            for (int i = 0; i < 4; i++) a[i] = As[ty*4+i][kk];
            float4 b0 = *(float4*)&Bs[kk][tx*8];
            float4 b1 = *(float4*)&Bs[kk][tx*8+4];
            float bb[8] = {b0.x,b0.y,b0.z,b0.w,b1.x,b1.y,b1.z,b1.w};
            #pragma unroll
            for (int i = 0; i < 4; i++)
                #pragma unroll
                for (int j = 0; j < 8; j++)
                    acc[i][j] = fmaf(a[i], bb[j], acc[i][j]);
        }
        __syncthreads();
    }
    float* outb = out + (size_t)b*CCH*NPTS;
    #pragma unroll
    for (int i = 0; i < 4; i++) {
        int o = o0 + ty*4 + i;
        float alpha = 1.f, beta = 0.f;
        if (gvec) { alpha = gvec[o] * rsqrtf(1.f + EPSBN); beta = bvec[o]*alpha + bevec[o]; }
        else if (bvec) beta = bvec[o];
        float vv[8];
        #pragma unroll
        for (int j = 0; j < 8; j++) {
            vv[j] = fmaf(acc[i][j], alpha, beta);
            if (relu) vv[j] = fmaxf(vv[j], 0.f);
        }
        float4 s0 = {vv[0],vv[1],vv[2],vv[3]}, s1 = {vv[4],vv[5],vv[6],vv[7]};
        float* p = &outb[(size_t)o*NPTS + n0 + tx*8];
        *(float4*)p = s0; *(float4*)(p+4) = s1;
    }
}

// ---------------- per-head GEMM (q/k/v), tile 64o(full) x 128n, K=64 ----------
__global__ __launch_bounds__(256)
void k_head(const float* __restrict__ Wbase, const float* __restrict__ in,
            float* __restrict__ out, const float* __restrict__ bias, int l) {
    __shared__ float As[64][64];    // direct W[o][c] copy
    __shared__ float Bs[64][128];   // [cc][nn]
    int n0 = blockIdx.x * 128, bh = blockIdx.y, hh = bh & (NH-1);
    int t = threadIdx.x, tx = t & 15, ty = t >> 4;
    const float* W   = Wbase + (size_t)(l*NH + hh) * HDIM * HDIM;
    const float* inb = in + (size_t)bh * HDIM * NPTS;
    #pragma unroll
    for (int r = 0; r < 4; r++)
        ((float4*)As)[t + r*256] = ((const float4*)W)[t + r*256];
    #pragma unroll
    for (int r = 0; r < 8; r++) {
        int idx = r*1024 + t*4;
        int cc = idx >> 7, nn = idx & 127;
        *(float4*)&Bs[cc][nn] = *(const float4*)&inb[(size_t)cc*NPTS + n0 + nn];
    }
    __syncthreads();
    float acc[4][8] = {};
    #pragma unroll
    for (int cc = 0; cc < 64; cc++) {
        float a[4];
        #pragma unroll
        for (int i = 0; i < 4; i++) a[i] = As[ty*4+i][cc];
        float4 b0 = *(float4*)&Bs[cc][tx*8];
        float4 b1 = *(float4*)&Bs[cc][tx*8+4];
        float bb[8] = {b0.x,b0.y,b0.z,b0.w,b1.x,b1.y,b1.z,b1.w};
        #pragma unroll
        for (int i = 0; i < 4; i++)
            #pragma unroll
            for (int j = 0; j < 8; j++)
                acc[i][j] = fmaf(a[i], bb[j], acc[i][j]);
    }
    float* outb = out + (size_t)bh * HDIM * NPTS;
    int vbase = (l*NH + hh) * HDIM;
    #pragma unroll
    for (int i = 0; i < 4; i++) {
        int o = ty*4 + i;
        float bb = bias ? bias[vbase + o] : 0.f;
        float4 s0 = {acc[i][0]+bb, acc[i][1]+bb, acc[i][2]+bb, acc[i][3]+bb};
        float4 s1 = {acc[i][4]+bb, acc[i][5]+bb, acc[i][6]+bb, acc[i][7]+bb};
        float* p = &outb[(size_t)o*NPTS + n0 + tx*8];
        *(float4*)p = s0; *(float4*)(p+4) = s1;
    }
}

// ---------------- scores: S[n][m] = sum_o q[o][n]k[o][m], 128x128 tiles --------
__global__ __launch_bounds__(256)
void k_scores(const float* __restrict__ q, const float* __restrict__ k,
              float* __restrict__ S) {
    __shared__ float Qs[8][128], Ks[8][128];
    int m0 = blockIdx.x * 128, n0 = blockIdx.y * 128, bh = blockIdx.z;
    int t = threadIdx.x, tx = t & 15, ty = t >> 4;
    const float* qb = q + (size_t)bh * HDIM * NPTS;
    const float* kb = k + (size_t)bh * HDIM * NPTS;
    float acc[8][8] = {};
    int lkk = t >> 5, lnn = (t & 31) * 4;
    for (int kc = 0; kc < HDIM; kc += 8) {
        *(float4*)&Qs[lkk][lnn] = *(const float4*)&qb[(size_t)(kc+lkk)*NPTS + n0 + lnn];
        *(float4*)&Ks[lkk][lnn] = *(const float4*)&kb[(size_t)(kc+lkk)*NPTS + m0 + lnn];
        __syncthreads();
        #pragma unroll
        for (int kk = 0; kk < 8; kk++) {
            float4 a0 = *(float4*)&Qs[kk][ty*8], a1 = *(float4*)&Qs[kk][ty*8+4];
            float4 b0 = *(float4*)&Ks[kk][tx*8], b1 = *(float4*)&Ks[kk][tx*8+4];
            float a[8]  = {a0.x,a0.y,a0.z,a0.w,a1.x,a1.y,a1.z,a1.w};
            float bb[8] = {b0.x,b0.y,b0.z,b0.w,b1.x,b1.y,b1.z,b1.w};
            #pragma unroll
            for (int i = 0; i < 8; i++)
                #pragma unroll
                for (int j = 0; j < 8; j++)
                    acc[i][j] = fmaf(a[i], bb[j], acc[i][j]);
        }
        __syncthreads();
    }
    float* Sb = S + (size_t)bh * NPTS * NPTS;
    #pragma unroll
    for (int i = 0; i < 8; i++) {
        float4 s0 = {acc[i][0],acc[i][1],acc[i][2],acc[i][3]};
        float4 s1 = {acc[i][4],acc[i][5],acc[i][6],acc[i][7]};
        float* p = &Sb[(size_t)(n0 + ty*8 + i)*NPTS + m0 + tx*8];
        *(float4*)p = s0; *(float4*)(p+4) = s1;
    }
}

// ------- row stats: mx[n], 1/rowsumexp[n]; also zero cs and xr ----------------
__global__ __launch_bounds__(256)
void k_rowstats(const float* __restrict__ S, float* __restrict__ mxv,
                float* __restrict__ rsv, float* __restrict__ cs,
                float* __restrict__ xr) {
    int bh = blockIdx.y, n = blockIdx.x, t = threadIdx.x;
    const float* row = S + ((size_t)bh*NPTS + n)*NPTS;
    float4 a = *(const float4*)(row + 4*t);
    float4 b = *(const float4*)(row + 1024 + 4*t);
    float mx = fmaxf(fmaxf(fmaxf(a.x,a.y),fmaxf(a.z,a.w)),
                     fmaxf(fmaxf(b.x,b.y),fmaxf(b.z,b.w)));
    #pragma unroll
    for (int o = 16; o > 0; o >>= 1) mx = fmaxf(mx, __shfl_xor_sync(0xffffffffu, mx, o));
    __shared__ float sm[8];
    int w = t >> 5, ln = t & 31;
    if (!ln) sm[w] = mx;
    __syncthreads();
    mx = sm[0];
    #pragma unroll
    for (int i = 1; i < 8; i++) mx = fmaxf(mx, sm[i]);
    float s = fexp(a.x-mx)+fexp(a.y-mx)+fexp(a.z-mx)+fexp(a.w-mx)
            + fexp(b.x-mx)+fexp(b.y-mx)+fexp(b.z-mx)+fexp(b.w-mx);
    #pragma unroll
    for (int o = 16; o > 0; o >>= 1) s += __shfl_xor_sync(0xffffffffu, s, o);
    __syncthreads();
    if (!ln) sm[w] = s;
    __syncthreads();
    if (t == 0) {
        float tot = sm[0]+sm[1]+sm[2]+sm[3]+sm[4]+sm[5]+sm[6]+sm[7];
        int idx = bh*NPTS + n;
        mxv[idx] = mx;
        rsv[idx] = 1.f / tot;
        cs[idx]  = 0.f;
    }
    // zero xr: 16384 blocks x 64 = 1M floats
    if (t < HDIM) xr[((size_t)bh*NPTS + n)*HDIM + t] = 0.f;
}

// ------- dcomp: xr += v @ P (split-K, exp on the fly) + colsum accumulation ----
__global__ __launch_bounds__(256)
void k_dcomp(const float* __restrict__ v, const float* __restrict__ S,
             const float* __restrict__ mxv, const float* __restrict__ rsv,
             float* __restrict__ xr, float* __restrict__ cs) {
    __shared__ float Vs[64][16];    // [cc][kk]
    __shared__ float Ps[16][128];   // [kk][mm]
    __shared__ float sst[2][KCH];   // mx, rinv for this k range
    int m0 = blockIdx.x * 128, bh = blockIdx.y, kc0 = blockIdx.z * KCH;
    int t = threadIdx.x, tx = t & 15, ty = t >> 4;
    const float* vb = v + (size_t)bh * HDIM * NPTS;
    const float* Sb = S + (size_t)bh * NPTS * NPTS;
    for (int r = t; r < KCH; r += 256) {
        sst[0][r] = mxv[bh*NPTS + kc0 + r];
        sst[1][r] = rsv[bh*NPTS + kc0 + r];
    }
    __syncthreads();
    float acc[4][8] = {};
    float bsum[4] = {0.f,0.f,0.f,0.f};
    int vcc = t >> 2, vkk = (t & 3) * 4;
    for (int kc = 0; kc < KCH; kc += 16) {
        *(float4*)&Vs[vcc][vkk] = *(const float4*)&vb[(size_t)vcc*NPTS + kc0 + kc + vkk];
        #pragma unroll
        for (int hf = 0; hf < 2; hf++) {
            int idx = hf*1024 + t*4;
            int kk = idx >> 7, mm = idx & 127;
            float4 sv = *(const float4*)&Sb[(size_t)(kc0+kc+kk)*NPTS + m0 + mm];
            float m_ = sst[0][kc+kk], ri = sst[1][kc+kk];
            float4 p;
            p.x = fexp(sv.x - m_) * ri;
            p.y = fexp(sv.y - m_) * ri;
            p.z = fexp(sv.z - m_) * ri;
            p.w = fexp(sv.w - m_) * ri;
            *(float4*)&Ps[kk][mm] = p;
            bsum[0] += p.x; bsum[1] += p.y; bsum[2] += p.z; bsum[3] += p.w;
        }
        __syncthreads();
        #pragma unroll
        for (int kk = 0; kk < 16; kk++) {
            float a[4];
            #pragma unroll
            for (int i = 0; i < 4; i++) a[i] = Vs[ty*4+i][kk];
            float4 b0 = *(float4*)&Ps[kk][tx*8];
            float4 b1 = *(float4*)&Ps[kk][tx*8+4];
            float bb[8] = {b0.x,b0.y,b0.z,b0.w,b1.x,b1.y,b1.z,b1.w};
            #pragma unroll
            for (int i = 0; i < 4; i++)
                #pragma unroll
                for (int j = 0; j < 8; j++)
                    acc[i][j] = fmaf(a[i], bb[j], acc[i][j]);
        }
        __syncthreads();
    }
    // colsum partials (each P element was loaded exactly once in this block)
    int mmq = (t & 31) * 4;
    #pragma unroll
    for (int j = 0; j < 4; j++) atomicAdd(&cs[bh*NPTS + m0 + mmq + j], bsum[j]);
    // xr partials
    float* xb = xr + (size_t)bh * HDIM * NPTS;
    #pragma unroll
    for (int i = 0; i < 4; i++)
        #pragma unroll
        for (int j = 0; j < 8; j++)
            atomicAdd(&xb[(size_t)(ty*4+i)*NPTS + m0 + tx*8 + j], acc[i][j]);
}

// ------- t-GEMM: B = h - xr/(1e-9+cs) built on the fly; h += relu(BN(t)) ------
__global__ __launch_bounds__(256)
void k_tgemm(const float* __restrict__ Wbase, float* __restrict__ h,
             const float* __restrict__ xr, const float* __restrict__ cs,
             const float* __restrict__ tb, const float* __restrict__ bng,
             const float* __restrict__ bnb, int l) {
    __shared__ float As[64][64];
    __shared__ float Bs[64][128];
    int n0 = blockIdx.x * 128, bh = blockIdx.y, hh = bh & (NH-1);
    int t = threadIdx.x, tx = t & 15, ty = t >> 4;
    const float* W = Wbase + (size_t)(l*NH + hh) * HDIM * HDIM;
    float* hb = h + (size_t)bh * HDIM * NPTS;
    const float* xb = xr + (size_t)bh * HDIM * NPTS;
    #pragma unroll
    for (int r = 0; r < 4; r++)
        ((float4*)As)[t + r*256] = ((const float4*)W)[t + r*256];
    #pragma unroll
    for (int r = 0; r < 8; r++) {
        int idx = r*1024 + t*4;
        int cc = idx >> 7, nn = idx & 127;
        float4 hv = *(const float4*)&hb[(size_t)cc*NPTS + n0 + nn];
        float4 xv = *(const float4*)&xb[(size_t)cc*NPTS + n0 + nn];
        float4 cv = *(const float4*)&cs[bh*NPTS + n0 + nn];
        float4 d;
        d.x = hv.x - xv.x / (1e-9f + cv.x);
        d.y = hv.y - xv.y / (1e-9f + cv.y);
        d.z = hv.z - xv.z / (1e-9f + cv.z);
        d.w = hv.w - xv.w / (1e-9f + cv.w);
        *(float4*)&Bs[cc][nn] = d;
    }
    __syncthreads();
    float acc[4][8] = {};
    #pragma unroll
    for (int cc = 0; cc < 64; cc++) {
        float a[4];
        #pragma unroll
        for (int i = 0; i < 4; i++) a[i] = As[ty*4+i][cc];
        float4 b0 = *(float4*)&Bs[cc][tx*8];
        float4 b1 = *(float4*)&Bs[cc][tx*8+4];
        float bb[8] = {b0.x,b0.y,b0.z,b0.w,b1.x,b1.y,b1.z,b1.w};
        #pragma unroll
        for (int i = 0; i < 4; i++)
            #pragma unroll
            for (int j = 0; j < 8; j++)
                acc[i][j] = fmaf(a[i], bb[j], acc[i][j]);
    }
    int vbase = (l*NH + hh) * HDIM;
    #pragma unroll
    for (int i = 0; i < 4; i++) {
        int o = ty*4 + i;
        float alpha = bng[vbase+o] * rsqrtf(1.f + EPSBN);
        float beta  = tb[vbase+o]*alpha + bnb[vbase+o];
        float* p = &hb[(size_t)o*NPTS + n0 + tx*8];
        float4 h0 = *(float4*)p, h1 = *(float4*)(p+4);
        h0.x += fmaxf(fmaf(acc[i][0], alpha, beta), 0.f);
        h0.y += fmaxf(fmaf(acc[i][1], alpha, beta), 0.f);
        h0.z += fmaxf(fmaf(acc[i][2], alpha, beta), 0.f);
        h0.w += fmaxf(fmaf(acc[i][3], alpha, beta), 0.f);
        h1.x += fmaxf(fmaf(acc[i][4], alpha, beta), 0.f);
        h1.y += fmaxf(fmaf(acc[i][5], alpha, beta), 0.f);
        h1.z += fmaxf(fmaf(acc[i][6], alpha, beta), 0.f);
        h1.w += fmaxf(fmaf(acc[i][7], alpha, beta), 0.f);
        *(float4*)p = h0; *(float4*)(p+4) = h1;
    }
}

// ---------------- host orchestration -------------------------------------------------
extern "C" void kernel_launch(void* const* d_in, const int* in_sizes, int n_in,
                              void* d_out, int out_size) {
    const float* x      = (const float*)d_in[0];
    const float* in_w1  = (const float*)d_in[1];
    const float* in_b1  = (const float*)d_in[2];
    const float* in_g1  = (const float*)d_in[3];
    const float* in_be1 = (const float*)d_in[4];
    const float* in_w2  = (const float*)d_in[5];
    const float* in_b2  = (const float*)d_in[6];
    const float* in_g2  = (const float*)d_in[7];
    const float* in_be2 = (const float*)d_in[8];
    const float* q_w    = (const float*)d_in[9];
    const float* k_w    = (const float*)d_in[10];
    const float* v_w    = (const float*)d_in[11];
    const float* v_b    = (const float*)d_in[12];
    const float* t_w    = (const float*)d_in[13];
    const float* t_b    = (const float*)d_in[14];
    const float* bn_g   = (const float*)d_in[15];
    const float* bn_b   = (const float*)d_in[16];
    const float* proj_w = (const float*)d_in[17];
    const float* proj_b = (const float*)d_in[18];

    float *hA, *hB, *qb, *kb, *vb, *xrb, *Sb, *mxv, *rsv, *csb;
    cudaGetSymbolAddress((void**)&hA,  g_bufA);
    cudaGetSymbolAddress((void**)&hB,  g_bufB);
    cudaGetSymbolAddress((void**)&qb,  g_q);
    cudaGetSymbolAddress((void**)&kb,  g_k);
    cudaGetSymbolAddress((void**)&vb,  g_v);
    cudaGetSymbolAddress((void**)&xrb, g_xr);
    cudaGetSymbolAddress((void**)&Sb,  g_S);
    cudaGetSymbolAddress((void**)&mxv, g_mx);
    cudaGetSymbolAddress((void**)&rsv, g_rs);
    cudaGetSymbolAddress((void**)&csb, g_cs);

    dim3 ttb(32, 8);
    k_transpose_in<<<dim3(NPTS/32, CCH/32, BNB), ttb>>>(x, hA);

    k_mlp<<<dim3(NPTS/128, CCH/64, BNB), 256>>>(in_w1, hA, hB, in_b1, in_g1, in_be1, 1);
    k_mlp<<<dim3(NPTS/128, CCH/64, BNB), 256>>>(in_w2, hB, hA, in_b2, in_g2, in_be2, 1);

    float* h = hA;
    float* o = hB;
    for (int l = 0; l < NL; l++) {
        k_head<<<dim3(NPTS/128, BHN), 256>>>(q_w, h, qb, nullptr, l);
        k_head<<<dim3(NPTS/128, BHN), 256>>>(k_w, h, kb, nullptr, l);
        k_head<<<dim3(NPTS/128, BHN), 256>>>(v_w, h, vb, v_b, l);

        k_scores  <<<dim3(NPTS/128, NPTS/128, BHN), 256>>>(qb, kb, Sb);
        k_rowstats<<<dim3(NPTS, BHN), 256>>>(Sb, mxv, rsv, csb, xrb);
        k_dcomp   <<<dim3(NPTS/128, BHN, KSPL), 256>>>(vb, Sb, mxv, rsv, xrb, csb);

        k_tgemm<<<dim3(NPTS/128, BHN), 256>>>(t_w, h, xrb, csb, t_b, bn_g, bn_b, l);
        k_mlp<<<dim3(NPTS/128, CCH/64, BNB), 256>>>(proj_w + (size_t)l*CCH*CCH, h, o,
                                                    proj_b + (size_t)l*CCH,
                                                    nullptr, nullptr, 0);
        float* tmp = h; h = o; o = tmp;
    }

    k_transpose_out<<<dim3(CCH/32, NPTS/32, BNB), ttb>>>(h, (float*)d_out);
}

// round 5
// speedup vs baseline: 1.7570x; 1.7570x over previous
#include <cuda_runtime.h>
#include <math.h>
#include <stdint.h>

#define BNB  2
#define NPTS 2048
#define CCH  256
#define NH   4
#define HDIM 64
#define NL   4
#define BHN  (BNB*NH)
#define EPSBN 1e-5f

// ---------------- scratch (device globals; no allocation allowed) -------------
__device__ float g_bufA[BNB*CCH*NPTS];
__device__ float g_bufB[BNB*CCH*NPTS];
__device__ float g_q  [BHN*HDIM*NPTS];
__device__ float g_k  [BHN*HDIM*NPTS];
__device__ float g_v  [BHN*HDIM*NPTS];
__device__ float g_d  [BHN*HDIM*NPTS];
__device__ float g_S  [(size_t)BHN*NPTS*NPTS];   // raw scores, 134 MB
__device__ float g_mx [BHN*NPTS];
__device__ float g_rs [BHN*NPTS];

// fast exp on the FMA pipe: exp(x) = 2^(x*log2e), |rel err| ~1e-7
__device__ __forceinline__ float fexp(float x) {
    x = fmaxf(x, -80.f);
    float t = fmaf(x, 1.44269504f, 12582912.f);
    int   e = __float_as_int(t) << 23;
    float r = t - 12582912.f;
    float f = fmaf(x, 1.44269504f, -r);
    float p = 1.54035304e-4f;
    p = fmaf(p, f, 1.33335581e-3f);
    p = fmaf(p, f, 9.61812911e-3f);
    p = fmaf(p, f, 5.55041087e-2f);
    p = fmaf(p, f, 2.40226507e-1f);
    p = fmaf(p, f, 6.93147181e-1f);
    p = fmaf(p, f, 1.0f);
    return __int_as_float(__float_as_int(p) + e);
}

__device__ __forceinline__ uint32_t tf32(float x) {
    uint32_t u;
    asm("cvt.rna.tf32.f32 %0, %1;" : "=r"(u) : "f"(x));
    return u;
}

#define MMA_TF32(c, a, b)                                                        \
    asm volatile("mma.sync.aligned.m16n8k8.row.col.f32.tf32.tf32.f32 "           \
                 "{%0,%1,%2,%3},{%4,%5,%6,%7},{%8,%9},{%0,%1,%2,%3};"            \
                 : "+f"((c)[0]), "+f"((c)[1]), "+f"((c)[2]), "+f"((c)[3])        \
                 : "r"((a)[0]), "r"((a)[1]), "r"((a)[2]), "r"((a)[3]),           \
                   "r"((b)[0]), "r"((b)[1]))

// ---------------- transposes ----------------
__global__ void k_transpose_in(const float* __restrict__ x, float* __restrict__ h) {
    __shared__ float tile[32][33];
    int b = blockIdx.z;
    int n0 = blockIdx.x * 32, c0 = blockIdx.y * 32;
    int tx = threadIdx.x, ty = threadIdx.y;
    for (int i = ty; i < 32; i += 8)
        tile[i][tx] = x[(size_t)b*NPTS*CCH + (size_t)(n0+i)*CCH + c0 + tx];
    __syncthreads();
    for (int i = ty; i < 32; i += 8)
        h[(size_t)b*CCH*NPTS + (size_t)(c0+i)*NPTS + n0 + tx] = tile[tx][i];
}

__global__ void k_transpose_out(const float* __restrict__ h, float* __restrict__ out) {
    __shared__ float tile[32][33];
    int b = blockIdx.z;
    int c0 = blockIdx.x * 32, n0 = blockIdx.y * 32;
    int tx = threadIdx.x, ty = threadIdx.y;
    for (int i = ty; i < 32; i += 8)
        tile[i][tx] = h[(size_t)b*CCH*NPTS + (size_t)(c0+i)*NPTS + n0 + tx];
    __syncthreads();
    for (int i = ty; i < 32; i += 8)
        out[(size_t)b*NPTS*CCH + (size_t)(n0+i)*CCH + c0 + tx] = tile[tx][i];
}

// ---------------- full-channel GEMM (MLP / proj), tile 64o x 128n, K step 16 ----
__global__ __launch_bounds__(256)
void k_mlp(const float* __restrict__ W, const float* __restrict__ in,
           float* __restrict__ out, const float* __restrict__ bvec,
           const float* __restrict__ gvec, const float* __restrict__ bevec,
           int relu) {
    __shared__ float As[64][16];
    __shared__ float Bs[16][128];
    int b  = blockIdx.z;
    int n0 = blockIdx.x * 128, o0 = blockIdx.y * 64;
    int t  = threadIdx.x, tx = t & 15, ty = t >> 4;
    const float* inb = in + (size_t)b*CCH*NPTS;
    int aoo = t >> 2, akk = (t & 3) * 4;
    float acc[4][8] = {};
    for (int kc = 0; kc < CCH; kc += 16) {
        *(float4*)&As[aoo][akk] = *(const float4*)&W[(size_t)(o0+aoo)*CCH + kc + akk];
        #pragma unroll
        for (int hf = 0; hf < 2; hf++) {
            int idx = hf*1024 + t*4;
            int kk = idx >> 7, nn = idx & 127;
            *(float4*)&Bs[kk][nn] = *(const float4*)&inb[(size_t)(kc+kk)*NPTS + n0 + nn];
        }
        __syncthreads();
        #pragma unroll
        for (int kk = 0; kk < 16; kk++) {
            float a[4];
            #pragma unroll
            for (int i = 0; i < 4; i++) a[i] = As[ty*4+i][kk];
            float4 b0 = *(float4*)&Bs[kk][tx*8];
            float4 b1 = *(float4*)&Bs[kk][tx*8+4];
            float bb[8] = {b0.x,b0.y,b0.z,b0.w,b1.x,b1.y,b1.z,b1.w};
            #pragma unroll
            for (int i = 0; i < 4; i++)
                #pragma unroll
                for (int j = 0; j < 8; j++)
                    acc[i][j] = fmaf(a[i], bb[j], acc[i][j]);
        }
        __syncthreads();
    }
    float* outb = out + (size_t)b*CCH*NPTS;
    #pragma unroll
    for (int i = 0; i < 4; i++) {
        int o = o0 + ty*4 + i;
        float alpha = 1.f, beta = 0.f;
        if (gvec) { alpha = gvec[o] * rsqrtf(1.f + EPSBN); beta = bvec[o]*alpha + bevec[o]; }
        else if (bvec) beta = bvec[o];
        float vv[8];
        #pragma unroll
        for (int j = 0; j < 8; j++) {
            vv[j] = fmaf(acc[i][j], alpha, beta);
            if (relu) vv[j] = fmaxf(vv[j], 0.f);
        }
        float4 s0 = {vv[0],vv[1],vv[2],vv[3]}, s1 = {vv[4],vv[5],vv[6],vv[7]};
        float* p = &outb[(size_t)o*NPTS + n0 + tx*8];
        *(float4*)p = s0; *(float4*)(p+4) = s1;
    }
}

// ---------------- per-head GEMM (q/k/v), tile 64o(full) x 128n, K=64 ----------
__global__ __launch_bounds__(256)
void k_head(const float* __restrict__ Wbase, const float* __restrict__ in,
            float* __restrict__ out, const float* __restrict__ bias, int l) {
    __shared__ float As[64][64];
    __shared__ float Bs[64][128];
    int n0 = blockIdx.x * 128, bh = blockIdx.y, hh = bh & (NH-1);
    int t = threadIdx.x, tx = t & 15, ty = t >> 4;
    const float* W   = Wbase + (size_t)(l*NH + hh) * HDIM * HDIM;
    const float* inb = in + (size_t)bh * HDIM * NPTS;
    #pragma unroll
    for (int r = 0; r < 4; r++)
        ((float4*)As)[t + r*256] = ((const float4*)W)[t + r*256];
    #pragma unroll
    for (int r = 0; r < 8; r++) {
        int idx = r*1024 + t*4;
        int cc = idx >> 7, nn = idx & 127;
        *(float4*)&Bs[cc][nn] = *(const float4*)&inb[(size_t)cc*NPTS + n0 + nn];
    }
    __syncthreads();
    float acc[4][8] = {};
    #pragma unroll
    for (int cc = 0; cc < 64; cc++) {
        float a[4];
        #pragma unroll
        for (int i = 0; i < 4; i++) a[i] = As[ty*4+i][cc];
        float4 b0 = *(float4*)&Bs[cc][tx*8];
        float4 b1 = *(float4*)&Bs[cc][tx*8+4];
        float bb[8] = {b0.x,b0.y,b0.z,b0.w,b1.x,b1.y,b1.z,b1.w};
        #pragma unroll
        for (int i = 0; i < 4; i++)
            #pragma unroll
            for (int j = 0; j < 8; j++)
                acc[i][j] = fmaf(a[i], bb[j], acc[i][j]);
    }
    float* outb = out + (size_t)bh * HDIM * NPTS;
    int vbase = (l*NH + hh) * HDIM;
    #pragma unroll
    for (int i = 0; i < 4; i++) {
        int o = ty*4 + i;
        float bb = bias ? bias[vbase + o] : 0.f;
        float4 s0 = {acc[i][0]+bb, acc[i][1]+bb, acc[i][2]+bb, acc[i][3]+bb};
        float4 s1 = {acc[i][4]+bb, acc[i][5]+bb, acc[i][6]+bb, acc[i][7]+bb};
        float* p = &outb[(size_t)o*NPTS + n0 + tx*8];
        *(float4*)p = s0; *(float4*)(p+4) = s1;
    }
}

// ---- scores (tensor core): S[n][m] = sum_o q[o][n] k[o][m], 128x128 tiles ----
__global__ __launch_bounds__(256)
void k_scores_tc(const float* __restrict__ q, const float* __restrict__ k,
                 float* __restrict__ S) {
    __shared__ uint32_t Qs[32][136];   // 136 % 32 == 8 -> conflict-free frags
    __shared__ uint32_t Ks[32][136];
    int m0 = blockIdx.x * 128, n0 = blockIdx.y * 128, bh = blockIdx.z;
    const float* qb = q + (size_t)bh * HDIM * NPTS;
    const float* kb = k + (size_t)bh * HDIM * NPTS;
    int t = threadIdx.x, warp = t >> 5, lane = t & 31;
    int wn = warp >> 2, wm = warp & 3;          // 2 x 4 warp grid: 64n x 32m each
    int gq = lane >> 2, tg = lane & 3;
    float acc[4][4][4];
    #pragma unroll
    for (int i = 0; i < 4; i++)
        #pragma unroll
        for (int j = 0; j < 4; j++)
            #pragma unroll
            for (int c = 0; c < 4; c++) acc[i][j][c] = 0.f;

    for (int kc = 0; kc < HDIM; kc += 32) {
        #pragma unroll
        for (int r = 0; r < 4; r++) {
            int idx = r*256 + t;
            int o = idx >> 5, nq = (idx & 31) * 4;
            float4 qv = *(const float4*)&qb[(size_t)(kc+o)*NPTS + n0 + nq];
            float4 kv = *(const float4*)&kb[(size_t)(kc+o)*NPTS + m0 + nq];
            uint4 qt = {tf32(qv.x), tf32(qv.y), tf32(qv.z), tf32(qv.w)};
            uint4 kt = {tf32(kv.x), tf32(kv.y), tf32(kv.z), tf32(kv.w)};
            *(uint4*)&Qs[o][nq] = qt;
            *(uint4*)&Ks[o][nq] = kt;
        }
        __syncthreads();
        #pragma unroll
        for (int k8 = 0; k8 < 32; k8 += 8) {
            uint32_t a[4][4], b[4][2];
            #pragma unroll
            for (int ti = 0; ti < 4; ti++) {
                int nb = wn*64 + ti*16 + gq;
                a[ti][0] = Qs[k8+tg][nb];
                a[ti][1] = Qs[k8+tg][nb+8];
                a[ti][2] = Qs[k8+4+tg][nb];
                a[ti][3] = Qs[k8+4+tg][nb+8];
            }
            #pragma unroll
            for (int tj = 0; tj < 4; tj++) {
                int mb = wm*32 + tj*8 + gq;
                b[tj][0] = Ks[k8+tg][mb];
                b[tj][1] = Ks[k8+4+tg][mb];
            }
            #pragma unroll
            for (int ti = 0; ti < 4; ti++)
                #pragma unroll
                for (int tj = 0; tj < 4; tj++)
                    MMA_TF32(acc[ti][tj], a[ti], b[tj]);
        }
        __syncthreads();
    }
    float* Sb = S + (size_t)bh * NPTS * NPTS;
    #pragma unroll
    for (int ti = 0; ti < 4; ti++) {
        #pragma unroll
        for (int tj = 0; tj < 4; tj++) {
            int n = n0 + wn*64 + ti*16 + gq;
            int m = m0 + wm*32 + tj*8 + 2*tg;
            float2 lo = {acc[ti][tj][0], acc[ti][tj][1]};
            float2 hi = {acc[ti][tj][2], acc[ti][tj][3]};
            *(float2*)&Sb[(size_t)n*NPTS + m]     = lo;
            *(float2*)&Sb[(size_t)(n+8)*NPTS + m] = hi;
        }
    }
}

// ------- row stats: mx[n], 1/rowsumexp[n] ----------------
__global__ __launch_bounds__(256)
void k_rowstats(const float* __restrict__ S, float* __restrict__ mxv,
                float* __restrict__ rsv) {
    int bh = blockIdx.y, n = blockIdx.x, t = threadIdx.x;
    const float* row = S + ((size_t)bh*NPTS + n)*NPTS;
    float4 a = *(const float4*)(row + 4*t);
    float4 b = *(const float4*)(row + 1024 + 4*t);
    float mx = fmaxf(fmaxf(fmaxf(a.x,a.y),fmaxf(a.z,a.w)),
                     fmaxf(fmaxf(b.x,b.y),fmaxf(b.z,b.w)));
    #pragma unroll
    for (int o = 16; o > 0; o >>= 1) mx = fmaxf(mx, __shfl_xor_sync(0xffffffffu, mx, o));
    __shared__ float sm[8];
    int w = t >> 5, ln = t & 31;
    if (!ln) sm[w] = mx;
    __syncthreads();
    mx = sm[0];
    #pragma unroll
    for (int i = 1; i < 8; i++) mx = fmaxf(mx, sm[i]);
    float s = fexp(a.x-mx)+fexp(a.y-mx)+fexp(a.z-mx)+fexp(a.w-mx)
            + fexp(b.x-mx)+fexp(b.y-mx)+fexp(b.z-mx)+fexp(b.w-mx);
    #pragma unroll
    for (int o = 16; o > 0; o >>= 1) s += __shfl_xor_sync(0xffffffffu, s, o);
    __syncthreads();
    if (!ln) sm[w] = s;
    __syncthreads();
    if (t == 0) {
        float tot = sm[0]+sm[1]+sm[2]+sm[3]+sm[4]+sm[5]+sm[6]+sm[7];
        int idx = bh*NPTS + n;
        mxv[idx] = mx;
        rsv[idx] = 1.f / tot;
    }
}

// ------- dcomp (tensor core, full-K): d = h - (v @ P) / colsum(P) -------------
// One block per (m-tile of 128, bh); K = 2048 covered fully -> local colsum.
__global__ __launch_bounds__(256)
void k_dcomp_tc(const float* __restrict__ v, const float* __restrict__ S,
                const float* __restrict__ mxv, const float* __restrict__ rsv,
                const float* __restrict__ h, float* __restrict__ d) {
    __shared__ uint32_t Vs[64][36];     // [c][kk], 36 -> conflict-free A frags
    __shared__ uint32_t Ps[32][136];    // [kk][m]
    __shared__ float red[8][128];
    __shared__ float csinv[128];
    int m0 = blockIdx.x * 128, bh = blockIdx.y;
    int t = threadIdx.x, warp = t >> 5, lane = t & 31;
    int wc = warp >> 2, wm = warp & 3;   // 2 x 4 grid: 32c x 32m per warp
    int gq = lane >> 2, tg = lane & 3;
    const float* vb = v + (size_t)bh * HDIM * NPTS;
    const float* Sb = S + (size_t)bh * NPTS * NPTS;
    float acc[2][4][4];
    #pragma unroll
    for (int i = 0; i < 2; i++)
        #pragma unroll
        for (int j = 0; j < 4; j++)
            #pragma unroll
            for (int c = 0; c < 4; c++) acc[i][j][c] = 0.f;
    float bsum[4] = {0.f, 0.f, 0.f, 0.f};

    for (int kc = 0; kc < NPTS; kc += 32) {
        // V tile 64 x 32
        #pragma unroll
        for (int r = 0; r < 2; r++) {
            int idx = r*256 + t;
            int c = idx >> 3, kq = (idx & 7) * 4;
            float4 vv = *(const float4*)&vb[(size_t)c*NPTS + kc + kq];
            uint4 vt = {tf32(vv.x), tf32(vv.y), tf32(vv.z), tf32(vv.w)};
            *(uint4*)&Vs[c][kq] = vt;
        }
        // S tile 32 x 128 -> P = exp(S-mx)*rinv (+ colsum partials)
        #pragma unroll
        for (int r = 0; r < 4; r++) {
            int idx = r*1024 + t*4;
            int kk = idx >> 7, mm = idx & 127;
            float4 sv = *(const float4*)&Sb[(size_t)(kc+kk)*NPTS + m0 + mm];
            float m_ = mxv[bh*NPTS + kc + kk];
            float ri = rsv[bh*NPTS + kc + kk];
            float p0 = fexp(sv.x - m_) * ri;
            float p1 = fexp(sv.y - m_) * ri;
            float p2 = fexp(sv.z - m_) * ri;
            float p3 = fexp(sv.w - m_) * ri;
            bsum[0] += p0; bsum[1] += p1; bsum[2] += p2; bsum[3] += p3;
            uint4 pt = {tf32(p0), tf32(p1), tf32(p2), tf32(p3)};
            *(uint4*)&Ps[kk][mm] = pt;
        }
        __syncthreads();
        #pragma unroll
        for (int k8 = 0; k8 < 32; k8 += 8) {
            uint32_t a[2][4], b[4][2];
            #pragma unroll
            for (int ti = 0; ti < 2; ti++) {
                int cb = wc*32 + ti*16 + gq;
                a[ti][0] = Vs[cb][k8+tg];
                a[ti][1] = Vs[cb+8][k8+tg];
                a[ti][2] = Vs[cb][k8+4+tg];
                a[ti][3] = Vs[cb+8][k8+4+tg];
            }
            #pragma unroll
            for (int tj = 0; tj < 4; tj++) {
                int mb = wm*32 + tj*8 + gq;
                b[tj][0] = Ps[k8+tg][mb];
                b[tj][1] = Ps[k8+4+tg][mb];
            }
            #pragma unroll
            for (int ti = 0; ti < 2; ti++)
                #pragma unroll
                for (int tj = 0; tj < 4; tj++)
                    MMA_TF32(acc[ti][tj], a[ti], b[tj]);
        }
        __syncthreads();
    }
    // local colsum reduction: thread's 4 columns are (t&31)*4 .. +3 for all chunks
    #pragma unroll
    for (int j = 0; j < 4; j++) red[t >> 5][(t & 31)*4 + j] = bsum[j];
    __syncthreads();
    if (t < 128) {
        float s = 0.f;
        #pragma unroll
        for (int w = 0; w < 8; w++) s += red[w][t];
        csinv[t] = 1.f / (1e-9f + s);
    }
    __syncthreads();
    // epilogue: d = h - acc * csinv
    const float* hb = h + (size_t)bh * HDIM * NPTS;
    float*       db = d + (size_t)bh * HDIM * NPTS;
    #pragma unroll
    for (int ti = 0; ti < 2; ti++) {
        #pragma unroll
        for (int tj = 0; tj < 4; tj++) {
            int c = wc*32 + ti*16 + gq;
            int mloc = wm*32 + tj*8 + 2*tg;
            float ci0 = csinv[mloc], ci1 = csinv[mloc+1];
            float2 h0 = *(const float2*)&hb[(size_t)c*NPTS + m0 + mloc];
            float2 h1 = *(const float2*)&hb[(size_t)(c+8)*NPTS + m0 + mloc];
            float2 d0 = {h0.x - acc[ti][tj][0]*ci0, h0.y - acc[ti][tj][1]*ci1};
            float2 d1 = {h1.x - acc[ti][tj][2]*ci0, h1.y - acc[ti][tj][3]*ci1};
            *(float2*)&db[(size_t)c*NPTS + m0 + mloc]     = d0;
            *(float2*)&db[(size_t)(c+8)*NPTS + m0 + mloc] = d1;
        }
    }
}

// ------- t-GEMM on d; h += relu(BN(t_w @ d + t_b)) ----------------------------
__global__ __launch_bounds__(256)
void k_tgemm(const float* __restrict__ Wbase, float* __restrict__ h,
             const float* __restrict__ d, const float* __restrict__ tb,
             const float* __restrict__ bng, const float* __restrict__ bnb, int l) {
    __shared__ float As[64][64];
    __shared__ float Bs[64][128];
    int n0 = blockIdx.x * 128, bh = blockIdx.y, hh = bh & (NH-1);
    int t = threadIdx.x, tx = t & 15, ty = t >> 4;
    const float* W = Wbase + (size_t)(l*NH + hh) * HDIM * HDIM;
    float* hb = h + (size_t)bh * HDIM * NPTS;
    const float* db = d + (size_t)bh * HDIM * NPTS;
    #pragma unroll
    for (int r = 0; r < 4; r++)
        ((float4*)As)[t + r*256] = ((const float4*)W)[t + r*256];
    #pragma unroll
    for (int r = 0; r < 8; r++) {
        int idx = r*1024 + t*4;
        int cc = idx >> 7, nn = idx & 127;
        *(float4*)&Bs[cc][nn] = *(const float4*)&db[(size_t)cc*NPTS + n0 + nn];
    }
    __syncthreads();
    float acc[4][8] = {};
    #pragma unroll
    for (int cc = 0; cc < 64; cc++) {
        float a[4];
        #pragma unroll
        for (int i = 0; i < 4; i++) a[i] = As[ty*4+i][cc];
        float4 b0 = *(float4*)&Bs[cc][tx*8];
        float4 b1 = *(float4*)&Bs[cc][tx*8+4];
        float bb[8] = {b0.x,b0.y,b0.z,b0.w,b1.x,b1.y,b1.z,b1.w};
        #pragma unroll
        for (int i = 0; i < 4; i++)
            #pragma unroll
            for (int j = 0; j < 8; j++)
                acc[i][j] = fmaf(a[i], bb[j], acc[i][j]);
    }
    int vbase = (l*NH + hh) * HDIM;
    #pragma unroll
    for (int i = 0; i < 4; i++) {
        int o = ty*4 + i;
        float alpha = bng[vbase+o] * rsqrtf(1.f + EPSBN);
        float beta  = tb[vbase+o]*alpha + bnb[vbase+o];
        float* p = &hb[(size_t)o*NPTS + n0 + tx*8];
        float4 h0 = *(float4*)p, h1 = *(float4*)(p+4);
        h0.x += fmaxf(fmaf(acc[i][0], alpha, beta), 0.f);
        h0.y += fmaxf(fmaf(acc[i][1], alpha, beta), 0.f);
        h0.z += fmaxf(fmaf(acc[i][2], alpha, beta), 0.f);
        h0.w += fmaxf(fmaf(acc[i][3], alpha, beta), 0.f);
        h1.x += fmaxf(fmaf(acc[i][4], alpha, beta), 0.f);
        h1.y += fmaxf(fmaf(acc[i][5], alpha, beta), 0.f);
        h1.z += fmaxf(fmaf(acc[i][6], alpha, beta), 0.f);
        h1.w += fmaxf(fmaf(acc[i][7], alpha, beta), 0.f);
        *(float4*)p = h0; *(float4*)(p+4) = h1;
    }
}

// ---------------- host orchestration -------------------------------------------------
extern "C" void kernel_launch(void* const* d_in, const int* in_sizes, int n_in,
                              void* d_out, int out_size) {
    const float* x      = (const float*)d_in[0];
    const float* in_w1  = (const float*)d_in[1];
    const float* in_b1  = (const float*)d_in[2];
    const float* in_g1  = (const float*)d_in[3];
    const float* in_be1 = (const float*)d_in[4];
    const float* in_w2  = (const float*)d_in[5];
    const float* in_b2  = (const float*)d_in[6];
    const float* in_g2  = (const float*)d_in[7];
    const float* in_be2 = (const float*)d_in[8];
    const float* q_w    = (const float*)d_in[9];
    const float* k_w    = (const float*)d_in[10];
    const float* v_w    = (const float*)d_in[11];
    const float* v_b    = (const float*)d_in[12];
    const float* t_w    = (const float*)d_in[13];
    const float* t_b    = (const float*)d_in[14];
    const float* bn_g   = (const float*)d_in[15];
    const float* bn_b   = (const float*)d_in[16];
    const float* proj_w = (const float*)d_in[17];
    const float* proj_b = (const float*)d_in[18];

    float *hA, *hB, *qb, *kb, *vb, *db, *Sb, *mxv, *rsv;
    cudaGetSymbolAddress((void**)&hA,  g_bufA);
    cudaGetSymbolAddress((void**)&hB,  g_bufB);
    cudaGetSymbolAddress((void**)&qb,  g_q);
    cudaGetSymbolAddress((void**)&kb,  g_k);
    cudaGetSymbolAddress((void**)&vb,  g_v);
    cudaGetSymbolAddress((void**)&db,  g_d);
    cudaGetSymbolAddress((void**)&Sb,  g_S);
    cudaGetSymbolAddress((void**)&mxv, g_mx);
    cudaGetSymbolAddress((void**)&rsv, g_rs);

    dim3 ttb(32, 8);
    k_transpose_in<<<dim3(NPTS/32, CCH/32, BNB), ttb>>>(x, hA);

    k_mlp<<<dim3(NPTS/128, CCH/64, BNB), 256>>>(in_w1, hA, hB, in_b1, in_g1, in_be1, 1);
    k_mlp<<<dim3(NPTS/128, CCH/64, BNB), 256>>>(in_w2, hB, hA, in_b2, in_g2, in_be2, 1);

    float* h = hA;
    float* o = hB;
    for (int l = 0; l < NL; l++) {
        k_head<<<dim3(NPTS/128, BHN), 256>>>(q_w, h, qb, nullptr, l);
        k_head<<<dim3(NPTS/128, BHN), 256>>>(k_w, h, kb, nullptr, l);
        k_head<<<dim3(NPTS/128, BHN), 256>>>(v_w, h, vb, v_b, l);

        k_scores_tc<<<dim3(NPTS/128, NPTS/128, BHN), 256>>>(qb, kb, Sb);
        k_rowstats <<<dim3(NPTS, BHN), 256>>>(Sb, mxv, rsv);
        k_dcomp_tc <<<dim3(NPTS/128, BHN), 256>>>(vb, Sb, mxv, rsv, h, db);

        k_tgemm<<<dim3(NPTS/128, BHN), 256>>>(t_w, h, db, t_b, bn_g, bn_b, l);
        k_mlp<<<dim3(NPTS/128, CCH/64, BNB), 256>>>(proj_w + (size_t)l*CCH*CCH, h, o,
                                                    proj_b + (size_t)l*CCH,
                                                    nullptr, nullptr, 0);
        float* tmp = h; h = o; o = tmp;
    }

    k_transpose_out<<<dim3(CCH/32, NPTS/32, BNB), ttb>>>(h, (float*)d_out);
}

// round 6
// speedup vs baseline: 2.4808x; 1.4120x over previous
#include <cuda_runtime.h>
#include <math.h>
#include <stdint.h>

#define BNB  2
#define NPTS 2048
#define CCH  256
#define NH   4
#define HDIM 64
#define NL   4
#define BHN  (BNB*NH)
#define EPSBN 1e-5f

// ---------------- scratch (device globals; no allocation allowed) -------------
__device__ float g_bufA[BNB*CCH*NPTS];
__device__ float g_bufB[BNB*CCH*NPTS];
__device__ float g_q  [BHN*HDIM*NPTS];
__device__ float g_k  [BHN*HDIM*NPTS];
__device__ float g_v  [BHN*HDIM*NPTS];
__device__ float g_S  [(size_t)BHN*NPTS*NPTS];   // raw scores, 134 MB
__device__ float g_mx [BHN*NPTS];
__device__ float g_rs [BHN*NPTS];

// fast exp on the FMA pipe: exp(x) = 2^(x*log2e), |rel err| ~1e-7
__device__ __forceinline__ float fexp(float x) {
    x = fmaxf(x, -80.f);
    float t = fmaf(x, 1.44269504f, 12582912.f);
    int   e = __float_as_int(t) << 23;
    float r = t - 12582912.f;
    float f = fmaf(x, 1.44269504f, -r);
    float p = 1.54035304e-4f;
    p = fmaf(p, f, 1.33335581e-3f);
    p = fmaf(p, f, 9.61812911e-3f);
    p = fmaf(p, f, 5.55041087e-2f);
    p = fmaf(p, f, 2.40226507e-1f);
    p = fmaf(p, f, 6.93147181e-1f);
    p = fmaf(p, f, 1.0f);
    return __int_as_float(__float_as_int(p) + e);
}

__device__ __forceinline__ uint32_t tf32(float x) {
    uint32_t u;
    asm("cvt.rna.tf32.f32 %0, %1;" : "=r"(u) : "f"(x));
    return u;
}

#define MMA_TF32(c, a, b)                                                        \
    asm volatile("mma.sync.aligned.m16n8k8.row.col.f32.tf32.tf32.f32 "           \
                 "{%0,%1,%2,%3},{%4,%5,%6,%7},{%8,%9},{%0,%1,%2,%3};"            \
                 : "+f"((c)[0]), "+f"((c)[1]), "+f"((c)[2]), "+f"((c)[3])        \
                 : "r"((a)[0]), "r"((a)[1]), "r"((a)[2]), "r"((a)[3]),           \
                   "r"((b)[0]), "r"((b)[1]))

// ---------------- transposes ----------------
__global__ void k_transpose_in(const float* __restrict__ x, float* __restrict__ h) {
    __shared__ float tile[32][33];
    int b = blockIdx.z;
    int n0 = blockIdx.x * 32, c0 = blockIdx.y * 32;
    int tx = threadIdx.x, ty = threadIdx.y;
    for (int i = ty; i < 32; i += 8)
        tile[i][tx] = x[(size_t)b*NPTS*CCH + (size_t)(n0+i)*CCH + c0 + tx];
    __syncthreads();
    for (int i = ty; i < 32; i += 8)
        h[(size_t)b*CCH*NPTS + (size_t)(c0+i)*NPTS + n0 + tx] = tile[tx][i];
}

__global__ void k_transpose_out(const float* __restrict__ h, float* __restrict__ out) {
    __shared__ float tile[32][33];
    int b = blockIdx.z;
    int c0 = blockIdx.x * 32, n0 = blockIdx.y * 32;
    int tx = threadIdx.x, ty = threadIdx.y;
    for (int i = ty; i < 32; i += 8)
        tile[i][tx] = h[(size_t)b*CCH*NPTS + (size_t)(c0+i)*NPTS + n0 + tx];
    __syncthreads();
    for (int i = ty; i < 32; i += 8)
        out[(size_t)b*NPTS*CCH + (size_t)(n0+i)*CCH + c0 + tx] = tile[tx][i];
}

// ---------------- full-channel GEMM (MLP / proj), tile 64o x 128n, K step 16 ----
__global__ __launch_bounds__(256)
void k_mlp(const float* __restrict__ W, const float* __restrict__ in,
           float* __restrict__ out, const float* __restrict__ bvec,
           const float* __restrict__ gvec, const float* __restrict__ bevec,
           int relu) {
    __shared__ float As[64][16];
    __shared__ float Bs[16][128];
    int b  = blockIdx.z;
    int n0 = blockIdx.x * 128, o0 = blockIdx.y * 64;
    int t  = threadIdx.x, tx = t & 15, ty = t >> 4;
    const float* inb = in + (size_t)b*CCH*NPTS;
    int aoo = t >> 2, akk = (t & 3) * 4;
    float acc[4][8] = {};
    for (int kc = 0; kc < CCH; kc += 16) {
        *(float4*)&As[aoo][akk] = *(const float4*)&W[(size_t)(o0+aoo)*CCH + kc + akk];
        #pragma unroll
        for (int hf = 0; hf < 2; hf++) {
            int idx = hf*1024 + t*4;
            int kk = idx >> 7, nn = idx & 127;
            *(float4*)&Bs[kk][nn] = *(const float4*)&inb[(size_t)(kc+kk)*NPTS + n0 + nn];
        }
        __syncthreads();
        #pragma unroll
        for (int kk = 0; kk < 16; kk++) {
            float a[4];
            #pragma unroll
            for (int i = 0; i < 4; i++) a[i] = As[ty*4+i][kk];
            float4 b0 = *(float4*)&Bs[kk][tx*8];
            float4 b1 = *(float4*)&Bs[kk][tx*8+4];
            float bb[8] = {b0.x,b0.y,b0.z,b0.w,b1.x,b1.y,b1.z,b1.w};
            #pragma unroll
            for (int i = 0; i < 4; i++)
                #pragma unroll
                for (int j = 0; j < 8; j++)
                    acc[i][j] = fmaf(a[i], bb[j], acc[i][j]);
        }
        __syncthreads();
    }
    float* outb = out + (size_t)b*CCH*NPTS;
    #pragma unroll
    for (int i = 0; i < 4; i++) {
        int o = o0 + ty*4 + i;
        float alpha = 1.f, beta = 0.f;
        if (gvec) { alpha = gvec[o] * rsqrtf(1.f + EPSBN); beta = bvec[o]*alpha + bevec[o]; }
        else if (bvec) beta = bvec[o];
        float vv[8];
        #pragma unroll
        for (int j = 0; j < 8; j++) {
            vv[j] = fmaf(acc[i][j], alpha, beta);
            if (relu) vv[j] = fmaxf(vv[j], 0.f);
        }
        float4 s0 = {vv[0],vv[1],vv[2],vv[3]}, s1 = {vv[4],vv[5],vv[6],vv[7]};
        float* p = &outb[(size_t)o*NPTS + n0 + tx*8];
        *(float4*)p = s0; *(float4*)(p+4) = s1;
    }
}

// ------- fused q/k/v head GEMMs: one B-tile load, three weight passes ----------
__global__ __launch_bounds__(256)
void k_qkv(const float* __restrict__ qw, const float* __restrict__ kw,
           const float* __restrict__ vw, const float* __restrict__ vbias,
           const float* __restrict__ in, float* __restrict__ qo,
           float* __restrict__ ko, float* __restrict__ vo, int l) {
    __shared__ float As[64][64];
    __shared__ float Bs[64][128];
    int n0 = blockIdx.x * 128, bh = blockIdx.y, hh = bh & (NH-1);
    int t = threadIdx.x, tx = t & 15, ty = t >> 4;
    const float* inb = in + (size_t)bh * HDIM * NPTS;
    int vbase = (l*NH + hh) * HDIM;
    #pragma unroll
    for (int r = 0; r < 8; r++) {
        int idx = r*1024 + t*4;
        int cc = idx >> 7, nn = idx & 127;
        *(float4*)&Bs[cc][nn] = *(const float4*)&inb[(size_t)cc*NPTS + n0 + nn];
    }
    for (int w = 0; w < 3; w++) {
        const float* W = (w == 0 ? qw : w == 1 ? kw : vw) + (size_t)(l*NH + hh)*HDIM*HDIM;
        __syncthreads();   // previous pass done reading As (and Bs ready on 1st)
        #pragma unroll
        for (int r = 0; r < 4; r++)
            ((float4*)As)[t + r*256] = ((const float4*)W)[t + r*256];
        __syncthreads();
        float acc[4][8] = {};
        #pragma unroll
        for (int cc = 0; cc < 64; cc++) {
            float a[4];
            #pragma unroll
            for (int i = 0; i < 4; i++) a[i] = As[ty*4+i][cc];
            float4 b0 = *(float4*)&Bs[cc][tx*8];
            float4 b1 = *(float4*)&Bs[cc][tx*8+4];
            float bb[8] = {b0.x,b0.y,b0.z,b0.w,b1.x,b1.y,b1.z,b1.w};
            #pragma unroll
            for (int i = 0; i < 4; i++)
                #pragma unroll
                for (int j = 0; j < 8; j++)
                    acc[i][j] = fmaf(a[i], bb[j], acc[i][j]);
        }
        float* outb = (w == 0 ? qo : w == 1 ? ko : vo) + (size_t)bh * HDIM * NPTS;
        #pragma unroll
        for (int i = 0; i < 4; i++) {
            int o = ty*4 + i;
            float bb = (w == 2) ? vbias[vbase + o] : 0.f;
            float4 s0 = {acc[i][0]+bb, acc[i][1]+bb, acc[i][2]+bb, acc[i][3]+bb};
            float4 s1 = {acc[i][4]+bb, acc[i][5]+bb, acc[i][6]+bb, acc[i][7]+bb};
            float* p = &outb[(size_t)o*NPTS + n0 + tx*8];
            *(float4*)p = s0; *(float4*)(p+4) = s1;
        }
    }
}

// ---- scores + online row stats: block = 32 n-rows x full m (2048) -------------
// Writes raw S once; computes rowmax and 1/rowsumexp on the fly.
__global__ __launch_bounds__(256)
void k_scores_st(const float* __restrict__ q, const float* __restrict__ k,
                 float* __restrict__ S, float* __restrict__ mxv,
                 float* __restrict__ rsv) {
    __shared__ uint32_t Qs[64][40];    // [o][n], 40%32=8 -> conflict-free frags
    __shared__ uint32_t Ks[64][136];   // [o][m]
    __shared__ float Mred[32][8], Sred[32][8];
    int n0 = blockIdx.x * 32, bh = blockIdx.y;
    const float* qb = q + (size_t)bh * HDIM * NPTS;
    const float* kb = k + (size_t)bh * HDIM * NPTS;
    int t = threadIdx.x, warp = t >> 5, lane = t & 31;
    int wm = warp;                       // 8 warps: each 32n x 16m
    int gq = lane >> 2, tg = lane & 3;
    // Q tile 64o x 32n, loaded once
    #pragma unroll
    for (int r = 0; r < 2; r++) {
        int idx = r*1024 + t*4;
        int o = idx >> 5, nq = idx & 31;
        float4 qv = *(const float4*)&qb[(size_t)o*NPTS + n0 + nq];
        uint4 qt = {tf32(qv.x), tf32(qv.y), tf32(qv.z), tf32(qv.w)};
        *(uint4*)&Qs[o][nq] = qt;
    }
    float stM[2][2], stS[2][2];
    #pragma unroll
    for (int i = 0; i < 2; i++)
        #pragma unroll
        for (int hf = 0; hf < 2; hf++) { stM[i][hf] = -1e30f; stS[i][hf] = 0.f; }
    float* Sb = S + (size_t)bh * NPTS * NPTS;

    for (int m0 = 0; m0 < NPTS; m0 += 128) {
        __syncthreads();    // previous MMA done reading Ks (and Qs ready on 1st)
        #pragma unroll
        for (int r = 0; r < 8; r++) {
            int idx = r*1024 + t*4;
            int o = idx >> 7, mq = idx & 127;
            float4 kv = *(const float4*)&kb[(size_t)o*NPTS + m0 + mq];
            uint4 kt = {tf32(kv.x), tf32(kv.y), tf32(kv.z), tf32(kv.w)};
            *(uint4*)&Ks[o][mq] = kt;
        }
        __syncthreads();
        float acc[2][2][4];
        #pragma unroll
        for (int i = 0; i < 2; i++)
            #pragma unroll
            for (int j = 0; j < 2; j++)
                #pragma unroll
                for (int c = 0; c < 4; c++) acc[i][j][c] = 0.f;
        #pragma unroll
        for (int k8 = 0; k8 < HDIM; k8 += 8) {
            uint32_t a[2][4], b[2][2];
            #pragma unroll
            for (int ti = 0; ti < 2; ti++) {
                int nb = ti*16 + gq;
                a[ti][0] = Qs[k8+tg][nb];
                a[ti][1] = Qs[k8+tg][nb+8];
                a[ti][2] = Qs[k8+4+tg][nb];
                a[ti][3] = Qs[k8+4+tg][nb+8];
            }
            #pragma unroll
            for (int tj = 0; tj < 2; tj++) {
                int mb = wm*16 + tj*8 + gq;
                b[tj][0] = Ks[k8+tg][mb];
                b[tj][1] = Ks[k8+4+tg][mb];
            }
            #pragma unroll
            for (int ti = 0; ti < 2; ti++)
                #pragma unroll
                for (int tj = 0; tj < 2; tj++)
                    MMA_TF32(acc[ti][tj], a[ti], b[tj]);
        }
        // store raw S + online stats update
        #pragma unroll
        for (int ti = 0; ti < 2; ti++) {
            #pragma unroll
            for (int tj = 0; tj < 2; tj++) {
                int n = n0 + ti*16 + gq;
                int m = m0 + wm*16 + tj*8 + 2*tg;
                float2 lo = {acc[ti][tj][0], acc[ti][tj][1]};
                float2 hi = {acc[ti][tj][2], acc[ti][tj][3]};
                *(float2*)&Sb[(size_t)n*NPTS + m]     = lo;
                *(float2*)&Sb[(size_t)(n+8)*NPTS + m] = hi;
            }
            #pragma unroll
            for (int hf = 0; hf < 2; hf++) {
                float v0 = acc[ti][0][2*hf], v1 = acc[ti][0][2*hf+1];
                float v2 = acc[ti][1][2*hf], v3 = acc[ti][1][2*hf+1];
                float tmax = fmaxf(fmaxf(v0, v1), fmaxf(v2, v3));
                float nM = fmaxf(stM[ti][hf], tmax);
                float s = stS[ti][hf] * fexp(stM[ti][hf] - nM);
                s += fexp(v0-nM) + fexp(v1-nM) + fexp(v2-nM) + fexp(v3-nM);
                stM[ti][hf] = nM; stS[ti][hf] = s;
            }
        }
    }
    // reduce stats: butterfly over tg lanes, then across the 8 warps
    #pragma unroll
    for (int ti = 0; ti < 2; ti++) {
        #pragma unroll
        for (int hf = 0; hf < 2; hf++) {
            float M = stM[ti][hf], Sm = stS[ti][hf];
            #pragma unroll
            for (int off = 1; off <= 2; off <<= 1) {
                float Mo = __shfl_xor_sync(0xffffffffu, M, off);
                float So = __shfl_xor_sync(0xffffffffu, Sm, off);
                float nM = fmaxf(M, Mo);
                Sm = Sm*fexp(M-nM) + So*fexp(Mo-nM);
                M = nM;
            }
            if (tg == 0) {
                int row = ti*16 + gq + 8*hf;
                Mred[row][wm] = M; Sred[row][wm] = Sm;
            }
        }
    }
    __syncthreads();
    if (t < 32) {
        float M = Mred[t][0], Sm = Sred[t][0];
        #pragma unroll
        for (int w = 1; w < 8; w++) {
            float Mo = Mred[t][w], So = Sred[t][w];
            float nM = fmaxf(M, Mo);
            Sm = Sm*fexp(M-nM) + So*fexp(Mo-nM);
            M = nM;
        }
        int idx = bh*NPTS + n0 + t;
        mxv[idx] = M;
        rsv[idx] = 1.f / Sm;
    }
}

// ------- mega dcomp: xr = v@P (tf32 MMA, full K) + colsum + d + t-GEMM + h update ---
// One block per (m-tile of 64, bh).  smem pool unions (Vs,Ps) with (Ws,Ds).
__global__ __launch_bounds__(256)
void k_dcomp_mega(const float* __restrict__ v, const float* __restrict__ S,
                  const float* __restrict__ mxv, const float* __restrict__ rsv,
                  const float* __restrict__ Wbase, float* __restrict__ h,
                  const float* __restrict__ tb, const float* __restrict__ bng,
                  const float* __restrict__ bnb, int l) {
    __shared__ uint32_t pool[8448];   // Vs[64][36] | Ps[32][68]  ==  Ws[64][64] | Ds[64][68]
    __shared__ float red[16][64];
    __shared__ float csinv[64];
    #define VSM(c,kk)  pool[(c)*36 + (kk)]
    #define PSM(kk,mm) pool[2304 + (kk)*68 + (mm)]
    #define WSM(o,c)   (((float*)pool)[(o)*64 + (c)])
    #define DSM(c,m)   (((float*)pool)[4096 + (c)*68 + (m)])
    int m0 = blockIdx.x * 64, bh = blockIdx.y, hh = bh & (NH-1);
    int t = threadIdx.x, warp = t >> 5, lane = t & 31;
    int wc = warp >> 2, wm = warp & 3;   // 2x4: each warp 32c x 16m
    int gq = lane >> 2, tg = lane & 3;
    const float* vb = v + (size_t)bh * HDIM * NPTS;
    const float* Sb = S + (size_t)bh * NPTS * NPTS;
    float* hb = h + (size_t)bh * HDIM * NPTS;
    float acc[2][2][4];
    #pragma unroll
    for (int i = 0; i < 2; i++)
        #pragma unroll
        for (int j = 0; j < 2; j++)
            #pragma unroll
            for (int c = 0; c < 4; c++) acc[i][j][c] = 0.f;
    float bsum[4] = {0.f, 0.f, 0.f, 0.f};

    for (int kc = 0; kc < NPTS; kc += 32) {
        if (kc) __syncthreads();        // previous MMA done reading Vs/Ps
        // V tile 64c x 32k
        #pragma unroll
        for (int r = 0; r < 2; r++) {
            int idx = r*256 + t;
            int c = idx >> 3, kq = (idx & 7) * 4;
            float4 vv = *(const float4*)&vb[(size_t)c*NPTS + kc + kq];
            uint4 vt = {tf32(vv.x), tf32(vv.y), tf32(vv.z), tf32(vv.w)};
            *(uint4*)&VSM(c, kq) = vt;
        }
        // S tile 32k x 64m -> P = exp(S - mx) * rinv, plus colsum partials
        #pragma unroll
        for (int r = 0; r < 2; r++) {
            int idx = r*1024 + t*4;
            int kk = idx >> 6, mm = idx & 63;
            float4 sv = *(const float4*)&Sb[(size_t)(kc+kk)*NPTS + m0 + mm];
            float m_ = mxv[bh*NPTS + kc + kk];
            float ri = rsv[bh*NPTS + kc + kk];
            float p0 = fexp(sv.x - m_) * ri;
            float p1 = fexp(sv.y - m_) * ri;
            float p2 = fexp(sv.z - m_) * ri;
            float p3 = fexp(sv.w - m_) * ri;
            bsum[0] += p0; bsum[1] += p1; bsum[2] += p2; bsum[3] += p3;
            uint4 pt = {tf32(p0), tf32(p1), tf32(p2), tf32(p3)};
            *(uint4*)&PSM(kk, mm) = pt;
        }
        __syncthreads();
        #pragma unroll
        for (int k8 = 0; k8 < 32; k8 += 8) {
            uint32_t a[2][4], b[2][2];
            #pragma unroll
            for (int ti = 0; ti < 2; ti++) {
                int cb = wc*32 + ti*16 + gq;
                a[ti][0] = VSM(cb,   k8+tg);
                a[ti][1] = VSM(cb+8, k8+tg);
                a[ti][2] = VSM(cb,   k8+4+tg);
                a[ti][3] = VSM(cb+8, k8+4+tg);
            }
            #pragma unroll
            for (int tj = 0; tj < 2; tj++) {
                int mb = wm*16 + tj*8 + gq;
                b[tj][0] = PSM(k8+tg,   mb);
                b[tj][1] = PSM(k8+4+tg, mb);
            }
            #pragma unroll
            for (int ti = 0; ti < 2; ti++)
                #pragma unroll
                for (int tj = 0; tj < 2; tj++)
                    MMA_TF32(acc[ti][tj], a[ti], b[tj]);
        }
    }
    __syncthreads();
    // colsum: thread's 4 columns are (t&15)*4 + j in both load passes
    #pragma unroll
    for (int j = 0; j < 4; j++) red[t >> 4][(t & 15)*4 + j] = bsum[j];
    __syncthreads();
    if (t < 64) {
        float s = 0.f;
        #pragma unroll
        for (int g = 0; g < 16; g++) s += red[g][t];
        csinv[t] = 1.f / (1e-9f + s);
    }
    __syncthreads();   // csinv ready; MMA/Ps reads done -> pool reusable
    // write d tile into Ds; load t_w into Ws
    #pragma unroll
    for (int r = 0; r < 4; r++) {
        float4 wv = ((const float4*)(Wbase + (size_t)(l*NH+hh)*HDIM*HDIM))[t + r*256];
        int wi = (t + r*256)*4;
        WSM(wi >> 6, wi & 63) = wv.x;
        WSM(wi >> 6, (wi & 63)+1) = wv.y;
        WSM(wi >> 6, (wi & 63)+2) = wv.z;
        WSM(wi >> 6, (wi & 63)+3) = wv.w;
    }
    #pragma unroll
    for (int ti = 0; ti < 2; ti++) {
        #pragma unroll
        for (int tj = 0; tj < 2; tj++) {
            int c = wc*32 + ti*16 + gq;
            int mloc = wm*16 + tj*8 + 2*tg;
            float ci0 = csinv[mloc], ci1 = csinv[mloc+1];
            float2 h0 = *(const float2*)&hb[(size_t)c*NPTS + m0 + mloc];
            float2 h1 = *(const float2*)&hb[(size_t)(c+8)*NPTS + m0 + mloc];
            DSM(c,   mloc)   = h0.x - acc[ti][tj][0]*ci0;
            DSM(c,   mloc+1) = h0.y - acc[ti][tj][1]*ci1;
            DSM(c+8, mloc)   = h1.x - acc[ti][tj][2]*ci0;
            DSM(c+8, mloc+1) = h1.y - acc[ti][tj][3]*ci1;
        }
    }
    __syncthreads();
    // t-GEMM 64x64x64 (FFMA) + BN + relu + residual into h
    {
        int tx = t & 15, ty = t >> 4;
        float acc2[4][4] = {};
        #pragma unroll
        for (int cc = 0; cc < 64; cc++) {
            float a[4];
            #pragma unroll
            for (int i = 0; i < 4; i++) a[i] = WSM(ty*4+i, cc);
            float4 bv = *(float4*)&DSM(cc, tx*4);
            float bb[4] = {bv.x, bv.y, bv.z, bv.w};
            #pragma unroll
            for (int i = 0; i < 4; i++)
                #pragma unroll
                for (int j = 0; j < 4; j++)
                    acc2[i][j] = fmaf(a[i], bb[j], acc2[i][j]);
        }
        int vbase = (l*NH + hh) * HDIM;
        #pragma unroll
        for (int i = 0; i < 4; i++) {
            int o = ty*4 + i;
            float alpha = bng[vbase+o] * rsqrtf(1.f + EPSBN);
            float beta  = tb[vbase+o]*alpha + bnb[vbase+o];
            float* p = &hb[(size_t)o*NPTS + m0 + tx*4];
            float4 hv = *(float4*)p;
            hv.x += fmaxf(fmaf(acc2[i][0], alpha, beta), 0.f);
            hv.y += fmaxf(fmaf(acc2[i][1], alpha, beta), 0.f);
            hv.z += fmaxf(fmaf(acc2[i][2], alpha, beta), 0.f);
            hv.w += fmaxf(fmaf(acc2[i][3], alpha, beta), 0.f);
            *(float4*)p = hv;
        }
    }
    #undef VSM
    #undef PSM
    #undef WSM
    #undef DSM
}

// ---------------- host orchestration -------------------------------------------------
extern "C" void kernel_launch(void* const* d_in, const int* in_sizes, int n_in,
                              void* d_out, int out_size) {
    const float* x      = (const float*)d_in[0];
    const float* in_w1  = (const float*)d_in[1];
    const float* in_b1  = (const float*)d_in[2];
    const float* in_g1  = (const float*)d_in[3];
    const float* in_be1 = (const float*)d_in[4];
    const float* in_w2  = (const float*)d_in[5];
    const float* in_b2  = (const float*)d_in[6];
    const float* in_g2  = (const float*)d_in[7];
    const float* in_be2 = (const float*)d_in[8];
    const float* q_w    = (const float*)d_in[9];
    const float* k_w    = (const float*)d_in[10];
    const float* v_w    = (const float*)d_in[11];
    const float* v_b    = (const float*)d_in[12];
    const float* t_w    = (const float*)d_in[13];
    const float* t_b    = (const float*)d_in[14];
    const float* bn_g   = (const float*)d_in[15];
    const float* bn_b   = (const float*)d_in[16];
    const float* proj_w = (const float*)d_in[17];
    const float* proj_b = (const float*)d_in[18];

    float *hA, *hB, *qb, *kb, *vb, *Sb, *mxv, *rsv;
    cudaGetSymbolAddress((void**)&hA,  g_bufA);
    cudaGetSymbolAddress((void**)&hB,  g_bufB);
    cudaGetSymbolAddress((void**)&qb,  g_q);
    cudaGetSymbolAddress((void**)&kb,  g_k);
    cudaGetSymbolAddress((void**)&vb,  g_v);
    cudaGetSymbolAddress((void**)&Sb,  g_S);
    cudaGetSymbolAddress((void**)&mxv, g_mx);
    cudaGetSymbolAddress((void**)&rsv, g_rs);

    dim3 ttb(32, 8);
    k_transpose_in<<<dim3(NPTS/32, CCH/32, BNB), ttb>>>(x, hA);

    k_mlp<<<dim3(NPTS/128, CCH/64, BNB), 256>>>(in_w1, hA, hB, in_b1, in_g1, in_be1, 1);
    k_mlp<<<dim3(NPTS/128, CCH/64, BNB), 256>>>(in_w2, hB, hA, in_b2, in_g2, in_be2, 1);

    float* h = hA;
    float* o = hB;
    for (int l = 0; l < NL; l++) {
        k_qkv<<<dim3(NPTS/128, BHN), 256>>>(q_w, k_w, v_w, v_b, h, qb, kb, vb, l);
        k_scores_st<<<dim3(NPTS/32, BHN), 256>>>(qb, kb, Sb, mxv, rsv);
        k_dcomp_mega<<<dim3(NPTS/64, BHN), 256>>>(vb, Sb, mxv, rsv, t_w, h,
                                                  t_b, bn_g, bn_b, l);
        k_mlp<<<dim3(NPTS/128, CCH/64, BNB), 256>>>(proj_w + (size_t)l*CCH*CCH, h, o,
                                                    proj_b + (size_t)l*CCH,
                                                    nullptr, nullptr, 0);
        float* tmp = h; h = o; o = tmp;
    }

    k_transpose_out<<<dim3(CCH/32, NPTS/32, BNB), ttb>>>(h, (float*)d_out);
}